// round 15
// baseline (speedup 1.0000x reference)
#include <cuda_runtime.h>
#include <cuda_fp16.h>
#include <cstdint>

#define Bb 2
#define Ss 2048
#define Dd 1024
#define Hh 16
#define DK 64
#define BH (Bb*Hh)       // 32
#define MROWS (Bb*Ss)    // 4096

// ---------------- device scratch (allocation-free rule) ----------------
__device__ __half g_wt_hi[4][(size_t)Dd * Dd];   // W^T [N,K] (B side)
__device__ __half g_wt_lo[4][(size_t)Dd * Dd];
__device__ __half g_x[3][(size_t)MROWS * Dd];    // inputs q,k,v (A side, hi only)
__device__ __half g_qh[(size_t)BH * Ss * DK];    // Q head-split (A side, hi only)
__device__ __half g_kh_hi[(size_t)BH * Ss * DK]; // K (B side)
__device__ __half g_kh_lo[(size_t)BH * Ss * DK];
__device__ __half g_vh_hi[(size_t)BH * Ss * DK]; // V (B side via vt)
__device__ __half g_vh_lo[(size_t)BH * Ss * DK];
__device__ __half g_vt_hi[(size_t)BH * DK * Ss]; // V^T [BH,dk,S]
__device__ __half g_vt_lo[(size_t)BH * DK * Ss];
__device__ __half g_sc[(size_t)BH * Ss * Ss];    // exp(scores) (A side, hi only)
__device__ __half g_ctx[(size_t)MROWS * Dd];     // ctx (A side, hi only)
__device__ float  g_rowsum[(size_t)BH * Ss];     // softmax denominators

// ---------------- helpers ----------------
__device__ __forceinline__ uint32_t smem_u32(const void* p) {
    uint32_t a;
    asm("{ .reg .u64 t; cvta.to.shared.u64 t, %1; cvt.u32.u64 %0, t; }" : "=r"(a) : "l"(p));
    return a;
}
__device__ __forceinline__ uint32_t pkh(float a, float b) {   // lo=a, hi=b
    uint32_t r;
    asm("cvt.rn.f16x2.f32 %0, %1, %2;" : "=r"(r) : "f"(b), "f"(a));
    return r;
}
__device__ __forceinline__ float2 uph(uint32_t v) {
    __half2 h = *reinterpret_cast<__half2*>(&v);
    return __half22float2(h);
}
__device__ __forceinline__ void splitp(float f0, float f1, uint32_t& hw, uint32_t& lw) {
    hw = pkh(f0, f1);
    float2 hb = uph(hw);
    lw = pkh(f0 - hb.x, f1 - hb.y);
}
__device__ __forceinline__ void ldm_x4(uint32_t (&r)[4], uint32_t addr) {
    asm volatile("ldmatrix.sync.aligned.m8n8.x4.shared.b16 {%0,%1,%2,%3}, [%4];"
        : "=r"(r[0]), "=r"(r[1]), "=r"(r[2]), "=r"(r[3]) : "r"(addr));
}
__device__ __forceinline__ void mma_f16(float (&c)[4], const uint32_t (&a)[4],
                                        uint32_t b0, uint32_t b1) {
    asm("mma.sync.aligned.m16n8k16.row.col.f32.f16.f16.f32 "
        "{%0,%1,%2,%3}, {%4,%5,%6,%7}, {%8,%9}, {%0,%1,%2,%3};"
        : "+f"(c[0]), "+f"(c[1]), "+f"(c[2]), "+f"(c[3])
        : "r"(a[0]), "r"(a[1]), "r"(a[2]), "r"(a[3]), "r"(b0), "r"(b1));
}
__device__ __forceinline__ void cpa16(uint32_t s, const void* g) {
    asm volatile("cp.async.cg.shared.global [%0], [%1], 16;" :: "r"(s), "l"(g));
}
#define CPA_COMMIT() asm volatile("cp.async.commit_group;" ::: "memory")
#define CPA_WAIT0()  asm volatile("cp.async.wait_group 0;" ::: "memory")
#define CPA_WAIT1()  asm volatile("cp.async.wait_group 1;" ::: "memory")

// warp tile 64m x 32n, one k16 step; asymmetric 2-product (A hi only, B hi+lo)
// 8 LDSM : 32 MMA
__device__ __forceinline__ void wtile4(
    float (&c)[4][4][4],
    uint32_t aH, uint32_t bH, uint32_t bL,
    int wm0, int wn0, int ks, uint32_t laneOfs, int stride)
{
    uint32_t ah[4][4], bh[2][4], bl[2][4];
    #pragma unroll
    for (int mf = 0; mf < 4; mf++)
        ldm_x4(ah[mf], aH + (wm0 + mf * 16) * stride + ks * 2 + laneOfs);
    #pragma unroll
    for (int np = 0; np < 2; np++) {
        ldm_x4(bh[np], bH + (wn0 + np * 16) * stride + ks * 2 + laneOfs);
        ldm_x4(bl[np], bL + (wn0 + np * 16) * stride + ks * 2 + laneOfs);
    }
    #pragma unroll
    for (int mf = 0; mf < 4; mf++)
        #pragma unroll
        for (int np = 0; np < 2; np++) {
            mma_f16(c[mf][2 * np],     ah[mf], bh[np][0], bh[np][2]);
            mma_f16(c[mf][2 * np + 1], ah[mf], bh[np][1], bh[np][3]);
        }
    #pragma unroll
    for (int mf = 0; mf < 4; mf++)
        #pragma unroll
        for (int np = 0; np < 2; np++) {
            mma_f16(c[mf][2 * np],     ah[mf], bl[np][0], bl[np][2]);
            mma_f16(c[mf][2 * np + 1], ah[mf], bl[np][1], bl[np][3]);
        }
}

// ===========================================================================
// prep_w / prep_x / zero_rs / vt (unchanged from R14)
// ===========================================================================
__global__ void __launch_bounds__(256) prep_w_kernel(
    const float* __restrict__ W0, const float* __restrict__ W1,
    const float* __restrict__ W2, const float* __restrict__ W3)
{
    const float* Wz[4] = {W0, W1, W2, W3};
    const float* W = Wz[blockIdx.z];
    uint32_t* out_hi = (uint32_t*)g_wt_hi[blockIdx.z];
    uint32_t* out_lo = (uint32_t*)g_wt_lo[blockIdx.z];

    __shared__ float ts[64][33];
    const int k0 = blockIdx.x * 64, n0 = blockIdx.y * 32, tx = threadIdx.x;

    #pragma unroll
    for (int j = 0; j < 8; j++) {
        const int idx = tx + j * 256;
        const int k = idx >> 5, n = idx & 31;
        ts[k][n] = W[(size_t)(k0 + k) * Dd + n0 + n];
    }
    __syncthreads();

    #pragma unroll
    for (int j = 0; j < 4; j++) {
        const int idx = tx + j * 256;
        const int n = idx >> 5, kp = idx & 31;
        uint32_t h, l;
        splitp(ts[2 * kp][n], ts[2 * kp + 1][n], h, l);
        const size_t o = (size_t)(n0 + n) * (Dd / 2) + (k0 >> 1) + kp;
        out_hi[o] = h;
        out_lo[o] = l;
    }
}

__global__ void __launch_bounds__(256) prep_x_kernel(
    const float* __restrict__ q, const float* __restrict__ k, const float* __restrict__ v)
{
    const int z = blockIdx.y;
    const float* X = (z == 0) ? q : (z == 1) ? k : v;
    const int row = blockIdx.x, tx = threadIdx.x;
    float4 x = *(const float4*)&X[(size_t)row * Dd + tx * 4];
    uint2 hi;
    hi.x = pkh(x.x, x.y);
    hi.y = pkh(x.z, x.w);
    *(uint2*)((char*)g_x[z] + (size_t)row * 2048 + tx * 8) = hi;
}

__global__ void __launch_bounds__(256) zero_rs_kernel()
{
    const int i = (blockIdx.x * 256 + threadIdx.x) * 4;
    *(float4*)&g_rowsum[i] = make_float4(0.f, 0.f, 0.f, 0.f);
}

__global__ void __launch_bounds__(256) vt_kernel()
{
    __shared__ unsigned short th[64][34];
    __shared__ unsigned short tl[64][34];
    const int s0 = blockIdx.x * 64, dk0 = blockIdx.y * 32, bh = blockIdx.z;
    const int tx = threadIdx.x;
    const uint32_t* vh_hi = (const uint32_t*)g_vh_hi;
    const uint32_t* vh_lo = (const uint32_t*)g_vh_lo;
    uint32_t* vt_hi = (uint32_t*)g_vt_hi;
    uint32_t* vt_lo = (uint32_t*)g_vt_lo;

    #pragma unroll
    for (int j = 0; j < 4; j++) {
        const int idx = tx + j * 256;
        const int sl = idx >> 4, du = idx & 15;
        const size_t src = ((size_t)(bh * Ss + s0 + sl) * DK + dk0) / 2 + du;
        *(uint32_t*)&th[sl][2 * du] = vh_hi[src];
        *(uint32_t*)&tl[sl][2 * du] = vh_lo[src];
    }
    __syncthreads();
    #pragma unroll
    for (int j = 0; j < 4; j++) {
        const int idx = tx + j * 256;
        const int dkl = idx >> 5, sp = idx & 31;
        const size_t dst = (size_t)(bh * DK + dk0 + dkl) * (Ss / 2) + (s0 >> 1) + sp;
        vt_hi[dst] = (uint32_t)th[2 * sp][dkl] | ((uint32_t)th[2 * sp + 1][dkl] << 16);
        vt_lo[dst] = (uint32_t)tl[2 * sp][dkl] | ((uint32_t)tl[2 * sp + 1][dkl] << 16);
    }
}

#define STRIDE 80
// stage: A hi 256 rows x 64B -> 20480 ; B hi 64x64B @20480 ; B lo @25600 ; 30720
#define G_STAGE 30720
#define G_BH 20480
#define G_BL 25600

// ===========================================================================
// qkv: Y = X@W + b -> head-split fp16 (Q: hi only; K,V: hi+lo).
// CTA 256m x 64n, 256 thr, 2 CTA/SM. grid (16 nt, 16 mt, 3). dyn smem 92160.
// ===========================================================================
__global__ void __launch_bounds__(256, 2) qkv_mma_kernel(
    const float* __restrict__ bq, const float* __restrict__ bk, const float* __restrict__ bv)
{
    extern __shared__ char sm[];
    const uint32_t sb = smem_u32(sm);

    const int z = blockIdx.z;
    const float* bias = (z == 0) ? bq : (z == 1) ? bk : bv;
    const char* XA = (const char*)g_x[z];
    const char* WtH = (const char*)g_wt_hi[z];
    const char* WtL = (const char*)g_wt_lo[z];
    char* Y_hi = (char*)((z == 0) ? g_qh : (z == 1) ? g_kh_hi : g_vh_hi);
    char* Y_lo = (char*)((z == 1) ? g_kh_lo : g_vh_lo);
    const bool twoPlane = (z != 0);

    const int tx = threadIdx.x, w = tx >> 5, lane = tx & 31;
    const int n0 = blockIdx.x * 64, m0 = blockIdx.y * 256;
    const int wm0 = (w & 3) * 64, wn0 = (w >> 2) * 32;
    const uint32_t laneOfs = (lane & 15) * STRIDE + (lane >> 4) * 16;

    const int arow = tx;                               // A: 256 rows, 64B each
    const int brow = tx >> 2, bcb = (tx & 3) * 16;     // B: 64 rows x 64B
    const size_t gar = (size_t)(m0 + arow) * 2048;
    const size_t gbr = (size_t)(n0 + brow) * 2048 + bcb;
    const uint32_t da = sb + arow * STRIDE;
    const uint32_t db = sb + brow * STRIDE + bcb;

    float c[4][4][4] = {};

    #pragma unroll
    for (int p = 0; p < 2; p++) {
        const int k2 = p * 64;
        #pragma unroll
        for (int u = 0; u < 4; u++)
            cpa16(da + p * G_STAGE + u * 16, XA + gar + k2 + u * 16);
        cpa16(db + p * G_STAGE + G_BH, WtH + gbr + k2);
        cpa16(db + p * G_STAGE + G_BL, WtL + gbr + k2);
        CPA_COMMIT();
    }

    for (int it = 0; it < 32; it++) {
        if (it == 31) { CPA_WAIT0(); } else { CPA_WAIT1(); }
        __syncthreads();
        if (it + 2 < 32) {
            const int st = (it + 2) % 3;
            const int k2 = (it + 2) * 64;
            #pragma unroll
            for (int u = 0; u < 4; u++)
                cpa16(da + st * G_STAGE + u * 16, XA + gar + k2 + u * 16);
            cpa16(db + st * G_STAGE + G_BH, WtH + gbr + k2);
            cpa16(db + st * G_STAGE + G_BL, WtL + gbr + k2);
            CPA_COMMIT();
        }
        const uint32_t cur = sb + (it % 3) * G_STAGE;
        wtile4(c, cur, cur + G_BH, cur + G_BL, wm0, wn0, 0,  laneOfs, STRIDE);
        wtile4(c, cur, cur + G_BH, cur + G_BL, wm0, wn0, 16, laneOfs, STRIDE);
    }

    const int g = lane >> 2, t2 = (lane & 3) * 2;
    #pragma unroll
    for (int mf = 0; mf < 4; mf++)
        #pragma unroll
        for (int nf = 0; nf < 4; nf++) {
            const int n = n0 + wn0 + nf * 8 + t2;
            const int h = n >> 6, dc = n & (DK - 1);
            const float bf0 = bias[n], bf1 = bias[n + 1];
            #pragma unroll
            for (int rr = 0; rr < 2; rr++) {
                const int m = m0 + wm0 + mf * 16 + g + rr * 8;
                const int bb = m >> 11, s = m & (Ss - 1);
                float f0 = c[mf][nf][2 * rr] + bf0;
                float f1 = c[mf][nf][2 * rr + 1] + bf1;
                const size_t eo = ((((size_t)(bb * Hh + h)) * Ss + s) * DK + dc) * 2;
                if (twoPlane) {
                    uint32_t hw, lw;
                    splitp(f0, f1, hw, lw);
                    *(uint32_t*)(Y_hi + eo) = hw;
                    *(uint32_t*)(Y_lo + eo) = lw;
                } else {
                    *(uint32_t*)(Y_hi + eo) = pkh(f0, f1);
                }
            }
        }
}

// ===========================================================================
// scores: e = exp(QK^T*0.125) -> fp16 hi plane + rowsums. CTA 256q x 64k.
// grid (32 kt, 8 qt, 32 bh), 256 thr, 2 CTA/SM. dyn smem 56320.
// Q @0 (256x144=36864), KH @36864 (9216), KL @46080 (9216), rowpart @55296
// ===========================================================================
#define SC_STRIDE 144
__global__ void __launch_bounds__(256, 2) scores_mma_kernel()
{
    extern __shared__ char sm[];
    const uint32_t sb = smem_u32(sm);
    float* rowpart = (float*)(sm + 55296);

    const int bh = blockIdx.z, tx = threadIdx.x, w = tx >> 5, lane = tx & 31;
    const int kb0 = blockIdx.x * 64, q0 = blockIdx.y * 256;
    const int wm0 = (w & 3) * 64, wn0 = (w >> 2) * 32;
    const uint32_t laneOfs = (lane & 15) * SC_STRIDE + (lane >> 4) * 16;

    const char* QA = (const char*)g_qh    + (size_t)bh * Ss * 128;
    const char* KH = (const char*)g_kh_hi + (size_t)bh * Ss * 128;
    const char* KL = (const char*)g_kh_lo + (size_t)bh * Ss * 128;

    rowpart[tx] = 0.f;

    #pragma unroll
    for (int j = 0; j < 8; j++) {           // Q hi: 256 rows x 128B
        const int idx = tx + j * 256;
        const int row = idx >> 3, cb = (idx & 7) * 16;
        cpa16(sb + row * SC_STRIDE + cb, QA + (size_t)(q0 + row) * 128 + cb);
    }
    #pragma unroll
    for (int j = 0; j < 2; j++) {           // K hi+lo: 64 rows x 128B each
        const int idx = tx + j * 256;
        const int row = idx >> 3, cb = (idx & 7) * 16;
        const uint32_t d = sb + 36864 + row * SC_STRIDE + cb;
        cpa16(d + 0,    KH + (size_t)(kb0 + row) * 128 + cb);
        cpa16(d + 9216, KL + (size_t)(kb0 + row) * 128 + cb);
    }
    CPA_COMMIT();
    CPA_WAIT0();
    __syncthreads();

    float c[4][4][4] = {};
    wtile4(c, sb, sb + 36864, sb + 46080, wm0, wn0, 0,  laneOfs, SC_STRIDE);
    wtile4(c, sb, sb + 36864, sb + 46080, wm0, wn0, 16, laneOfs, SC_STRIDE);
    wtile4(c, sb, sb + 36864, sb + 46080, wm0, wn0, 32, laneOfs, SC_STRIDE);
    wtile4(c, sb, sb + 36864, sb + 46080, wm0, wn0, 48, laneOfs, SC_STRIDE);

    const int g = lane >> 2, t2 = (lane & 3) * 2;
    char* SC = (char*)g_sc;
    float part[4][2] = {};
    #pragma unroll
    for (int mf = 0; mf < 4; mf++)
        #pragma unroll
        for (int nf = 0; nf < 4; nf++) {
            const int kc = kb0 + wn0 + nf * 8 + t2;
            #pragma unroll
            for (int rr = 0; rr < 2; rr++) {
                const int qr = q0 + wm0 + mf * 16 + g + rr * 8;
                float e0 = __expf(c[mf][nf][2 * rr] * 0.125f);
                float e1 = __expf(c[mf][nf][2 * rr + 1] * 0.125f);
                part[mf][rr] += e0 + e1;
                const size_t eo = (((size_t)bh * Ss + qr) * Ss + kc) * 2;
                *(uint32_t*)(SC + eo) = pkh(e0, e1);
            }
        }
    #pragma unroll
    for (int mf = 0; mf < 4; mf++)
        #pragma unroll
        for (int rr = 0; rr < 2; rr++) {
            float p = part[mf][rr];
            p += __shfl_xor_sync(~0u, p, 1);
            p += __shfl_xor_sync(~0u, p, 2);
            if ((lane & 3) == 0)
                atomicAdd(&rowpart[wm0 + mf * 16 + rr * 8 + g], p);
        }
    __syncthreads();
    atomicAdd(&g_rowsum[(size_t)bh * Ss + q0 + tx], rowpart[tx]);
}

// ===========================================================================
// ctx: C = (P@V)/s -> fp16 hi plane; writes normalized attn fp32.
// CTA 256m x 64n, 256 thr, 2 CTA/SM. grid (8 mt, 32 bh). dyn smem 93184.
// stage = G_STAGE; inv_s @92160 (256 floats)
// ===========================================================================
__global__ void __launch_bounds__(256, 2) ctx_mma_kernel(float* __restrict__ attn)
{
    extern __shared__ char sm[];
    const uint32_t sb = smem_u32(sm);
    float* inv_s = (float*)(sm + 92160);

    const int bh = blockIdx.y, tx = threadIdx.x, w = tx >> 5, lane = tx & 31;
    const int m0 = blockIdx.x * 256;
    const int wm0 = (w & 3) * 64, wn0 = (w >> 2) * 32;
    const uint32_t laneOfs = (lane & 15) * STRIDE + (lane >> 4) * 16;

    const char* SC  = (const char*)g_sc    + (size_t)bh * Ss * 4096;
    const char* VTH = (const char*)g_vt_hi + (size_t)bh * DK * 4096;
    const char* VTL = (const char*)g_vt_lo + (size_t)bh * DK * 4096;

    inv_s[tx] = 1.0f / g_rowsum[(size_t)bh * Ss + m0 + tx];

    const int arow = tx;
    const int brow = tx >> 2, bcb = (tx & 3) * 16;
    const size_t gar = (size_t)(m0 + arow) * 4096;
    const size_t gbr = (size_t)brow * 4096 + bcb;
    const uint32_t da = sb + arow * STRIDE;
    const uint32_t db = sb + brow * STRIDE + bcb;

    float c[4][4][4] = {};

    #pragma unroll
    for (int p = 0; p < 2; p++) {
        const int k2 = p * 64;
        #pragma unroll
        for (int u = 0; u < 4; u++)
            cpa16(da + p * G_STAGE + u * 16, SC + gar + k2 + u * 16);
        cpa16(db + p * G_STAGE + G_BH, VTH + gbr + k2);
        cpa16(db + p * G_STAGE + G_BL, VTL + gbr + k2);
        CPA_COMMIT();
    }

    for (int it = 0; it < 64; it++) {
        if (it == 63) { CPA_WAIT0(); } else { CPA_WAIT1(); }
        __syncthreads();
        if (it + 2 < 64) {
            const int st = (it + 2) % 3;
            const int k2 = (it + 2) * 64;
            #pragma unroll
            for (int u = 0; u < 4; u++)
                cpa16(da + st * G_STAGE + u * 16, SC + gar + k2 + u * 16);
            cpa16(db + st * G_STAGE + G_BH, VTH + gbr + k2);
            cpa16(db + st * G_STAGE + G_BL, VTL + gbr + k2);
            CPA_COMMIT();
        }
        const int st = it % 3;
        const uint32_t cur = sb + st * G_STAGE;
        const int k0 = it * 32;

        // normalized attn fp32 write for this 256x32 block (from A hi smem)
        #pragma unroll
        for (int j = 0; j < 4; j++) {
            const int idx = tx + j * 256;
            const int row = idx >> 2, c8 = (idx & 3) * 8;
            uint2 hv = *(uint2*)(sm + st * G_STAGE + row * STRIDE + c8 * 2);
            const float is = inv_s[row];
            float2 p0 = uph(hv.x), p1 = uph(hv.y);
            float4 o0 = make_float4(p0.x * is, p0.y * is, p1.x * is, p1.y * is);
            uint2 hv2 = *(uint2*)(sm + st * G_STAGE + row * STRIDE + c8 * 2 + 8);
            float2 p2 = uph(hv2.x), p3 = uph(hv2.y);
            float4 o1 = make_float4(p2.x * is, p2.y * is, p3.x * is, p3.y * is);
            float* dst = &attn[((size_t)bh * Ss + m0 + row) * Ss + k0 + c8];
            *(float4*)dst = o0;
            *(float4*)(dst + 4) = o1;
        }

        wtile4(c, cur, cur + G_BH, cur + G_BL, wm0, wn0, 0,  laneOfs, STRIDE);
        wtile4(c, cur, cur + G_BH, cur + G_BL, wm0, wn0, 16, laneOfs, STRIDE);
    }

    const int g = lane >> 2, t2 = (lane & 3) * 2;
    const int b = bh >> 4, h = bh & (Hh - 1);
    #pragma unroll
    for (int mf = 0; mf < 4; mf++)
        #pragma unroll
        for (int nf = 0; nf < 4; nf++) {
            const int dc = wn0 + nf * 8 + t2;
            #pragma unroll
            for (int rr = 0; rr < 2; rr++) {
                const int sl = wm0 + mf * 16 + g + rr * 8;
                const float is = inv_s[sl];
                float f0 = c[mf][nf][2 * rr] * is;
                float f1 = c[mf][nf][2 * rr + 1] * is;
                const size_t eo = (((size_t)(b * Ss + m0 + sl)) * Dd + h * DK + dc) * 2;
                *(uint32_t*)((char*)g_ctx + eo) = pkh(f0, f1);
            }
        }
}

// ===========================================================================
// out: out = ctx @ W_o + b_o fp32. CTA 256m x 64n, 256 thr, 2 CTA/SM.
// grid (16 nt, 16 mt). dyn smem 92160.
// ===========================================================================
__global__ void __launch_bounds__(256, 2) out_mma_kernel(
    const float* __restrict__ bias, float* __restrict__ out)
{
    extern __shared__ char sm[];
    const uint32_t sb = smem_u32(sm);

    const int tx = threadIdx.x, w = tx >> 5, lane = tx & 31;
    const int n0 = blockIdx.x * 64, m0 = blockIdx.y * 256;
    const int wm0 = (w & 3) * 64, wn0 = (w >> 2) * 32;
    const uint32_t laneOfs = (lane & 15) * STRIDE + (lane >> 4) * 16;

    const char* CA = (const char*)g_ctx;
    const char* WtH = (const char*)g_wt_hi[3];
    const char* WtL = (const char*)g_wt_lo[3];

    const int arow = tx;
    const int brow = tx >> 2, bcb = (tx & 3) * 16;
    const size_t gar = (size_t)(m0 + arow) * 2048;
    const size_t gbr = (size_t)(n0 + brow) * 2048 + bcb;
    const uint32_t da = sb + arow * STRIDE;
    const uint32_t db = sb + brow * STRIDE + bcb;

    float c[4][4][4] = {};

    #pragma unroll
    for (int p = 0; p < 2; p++) {
        const int k2 = p * 64;
        #pragma unroll
        for (int u = 0; u < 4; u++)
            cpa16(da + p * G_STAGE + u * 16, CA + gar + k2 + u * 16);
        cpa16(db + p * G_STAGE + G_BH, WtH + gbr + k2);
        cpa16(db + p * G_STAGE + G_BL, WtL + gbr + k2);
        CPA_COMMIT();
    }

    for (int it = 0; it < 32; it++) {
        if (it == 31) { CPA_WAIT0(); } else { CPA_WAIT1(); }
        __syncthreads();
        if (it + 2 < 32) {
            const int st = (it + 2) % 3;
            const int k2 = (it + 2) * 64;
            #pragma unroll
            for (int u = 0; u < 4; u++)
                cpa16(da + st * G_STAGE + u * 16, CA + gar + k2 + u * 16);
            cpa16(db + st * G_STAGE + G_BH, WtH + gbr + k2);
            cpa16(db + st * G_STAGE + G_BL, WtL + gbr + k2);
            CPA_COMMIT();
        }
        const uint32_t cur = sb + (it % 3) * G_STAGE;
        wtile4(c, cur, cur + G_BH, cur + G_BL, wm0, wn0, 0,  laneOfs, STRIDE);
        wtile4(c, cur, cur + G_BH, cur + G_BL, wm0, wn0, 16, laneOfs, STRIDE);
    }

    const int g = lane >> 2, t2 = (lane & 3) * 2;
    #pragma unroll
    for (int mf = 0; mf < 4; mf++)
        #pragma unroll
        for (int nf = 0; nf < 4; nf++) {
            const int n = n0 + wn0 + nf * 8 + t2;
            const float bf0 = bias[n], bf1 = bias[n + 1];
            #pragma unroll
            for (int rr = 0; rr < 2; rr++) {
                const int m = m0 + wm0 + mf * 16 + g + rr * 8;
                float2 val = make_float2(c[mf][nf][2 * rr] + bf0,
                                         c[mf][nf][2 * rr + 1] + bf1);
                *(float2*)&out[(size_t)m * Dd + n] = val;
            }
        }
}

// ===========================================================================
extern "C" void kernel_launch(void* const* d_in, const int* in_sizes, int n_in,
                              void* d_out, int out_size)
{
    const float* q   = (const float*)d_in[0];
    const float* k   = (const float*)d_in[1];
    const float* v   = (const float*)d_in[2];
    const float* W_q = (const float*)d_in[3];
    const float* b_q = (const float*)d_in[4];
    const float* W_k = (const float*)d_in[5];
    const float* b_k = (const float*)d_in[6];
    const float* W_v = (const float*)d_in[7];
    const float* b_v = (const float*)d_in[8];
    const float* W_o = (const float*)d_in[9];
    const float* b_o = (const float*)d_in[10];

    float* out  = (float*)d_out;
    float* attn = out + (size_t)Bb * Ss * Dd;

    static int smem_set = 0;
    if (!smem_set) {
        cudaFuncSetAttribute(qkv_mma_kernel,    cudaFuncAttributeMaxDynamicSharedMemorySize, 92160);
        cudaFuncSetAttribute(scores_mma_kernel, cudaFuncAttributeMaxDynamicSharedMemorySize, 56320);
        cudaFuncSetAttribute(ctx_mma_kernel,    cudaFuncAttributeMaxDynamicSharedMemorySize, 93184);
        cudaFuncSetAttribute(out_mma_kernel,    cudaFuncAttributeMaxDynamicSharedMemorySize, 92160);
        smem_set = 1;
    }

    prep_w_kernel<<<dim3(16, 32, 4), 256>>>(W_q, W_k, W_v, W_o);
    prep_x_kernel<<<dim3(4096, 3), 256>>>(q, k, v);
    zero_rs_kernel<<<64, 256>>>();
    qkv_mma_kernel<<<dim3(16, 16, 3), 256, 92160>>>(b_q, b_k, b_v);
    vt_kernel<<<dim3(32, 2, 32), 256>>>();
    scores_mma_kernel<<<dim3(32, 8, 32), 256, 56320>>>();
    ctx_mma_kernel<<<dim3(8, 32), 256, 93184>>>(attn);
    out_mma_kernel<<<dim3(16, 16), 256, 92160>>>(b_o, out);
}

// round 16
// speedup vs baseline: 1.1362x; 1.1362x over previous
#include <cuda_runtime.h>
#include <cuda_fp16.h>
#include <cstdint>

#define Bb 2
#define Ss 2048
#define Dd 1024
#define Hh 16
#define DK 64
#define BH (Bb*Hh)       // 32
#define MROWS (Bb*Ss)    // 4096

// ---------------- device scratch (allocation-free rule) ----------------
__device__ __half g_wt_hi[4][(size_t)Dd * Dd];   // W^T [N,K] (B side)
__device__ __half g_wt_lo[4][(size_t)Dd * Dd];
__device__ __half g_x[3][(size_t)MROWS * Dd];    // inputs q,k,v (A side, hi only)
__device__ __half g_qh[(size_t)BH * Ss * DK];    // Q head-split (A side, hi only)
__device__ __half g_kh_hi[(size_t)BH * Ss * DK]; // K (B side)
__device__ __half g_kh_lo[(size_t)BH * Ss * DK];
__device__ __half g_vt_hi[(size_t)BH * DK * Ss]; // V^T [BH,dk,S] (written by qkv)
__device__ __half g_vt_lo[(size_t)BH * DK * Ss];
__device__ __half g_sc[(size_t)BH * Ss * Ss];    // exp(scores) (A side, hi only)
__device__ __half g_ctx[(size_t)MROWS * Dd];     // ctx (A side, hi only)
__device__ float  g_rowsum[(size_t)BH * Ss];     // softmax denominators

// ---------------- helpers ----------------
__device__ __forceinline__ uint32_t smem_u32(const void* p) {
    uint32_t a;
    asm("{ .reg .u64 t; cvta.to.shared.u64 t, %1; cvt.u32.u64 %0, t; }" : "=r"(a) : "l"(p));
    return a;
}
__device__ __forceinline__ uint32_t pkh(float a, float b) {   // lo=a, hi=b
    uint32_t r;
    asm("cvt.rn.f16x2.f32 %0, %1, %2;" : "=r"(r) : "f"(b), "f"(a));
    return r;
}
__device__ __forceinline__ float2 uph(uint32_t v) {
    __half2 h = *reinterpret_cast<__half2*>(&v);
    return __half22float2(h);
}
__device__ __forceinline__ void splitp(float f0, float f1, uint32_t& hw, uint32_t& lw) {
    hw = pkh(f0, f1);
    float2 hb = uph(hw);
    lw = pkh(f0 - hb.x, f1 - hb.y);
}
__device__ __forceinline__ void ldm_x4(uint32_t (&r)[4], uint32_t addr) {
    asm volatile("ldmatrix.sync.aligned.m8n8.x4.shared.b16 {%0,%1,%2,%3}, [%4];"
        : "=r"(r[0]), "=r"(r[1]), "=r"(r[2]), "=r"(r[3]) : "r"(addr));
}
__device__ __forceinline__ void mma_f16(float (&c)[4], const uint32_t (&a)[4],
                                        uint32_t b0, uint32_t b1) {
    asm("mma.sync.aligned.m16n8k16.row.col.f32.f16.f16.f32 "
        "{%0,%1,%2,%3}, {%4,%5,%6,%7}, {%8,%9}, {%0,%1,%2,%3};"
        : "+f"(c[0]), "+f"(c[1]), "+f"(c[2]), "+f"(c[3])
        : "r"(a[0]), "r"(a[1]), "r"(a[2]), "r"(a[3]), "r"(b0), "r"(b1));
}
__device__ __forceinline__ void cpa16(uint32_t s, const void* g) {
    asm volatile("cp.async.cg.shared.global [%0], [%1], 16;" :: "r"(s), "l"(g));
}
#define CPA_COMMIT() asm volatile("cp.async.commit_group;" ::: "memory")
#define CPA_WAIT0()  asm volatile("cp.async.wait_group 0;" ::: "memory")
#define CPA_WAIT1()  asm volatile("cp.async.wait_group 1;" ::: "memory")

// warp tile 32x32, one k16 step; asymmetric 2-product (A hi only, B hi+lo)
__device__ __forceinline__ void wtile2(
    float (&c)[2][4][4],
    uint32_t aH, uint32_t bH, uint32_t bL,
    int wm0, int wn0, int ks, uint32_t laneOfs, int stride)
{
    uint32_t ah[2][4], bh[2][4], bl[2][4];
    #pragma unroll
    for (int mf = 0; mf < 2; mf++)
        ldm_x4(ah[mf], aH + (wm0 + mf * 16) * stride + ks * 2 + laneOfs);
    #pragma unroll
    for (int np = 0; np < 2; np++) {
        ldm_x4(bh[np], bH + (wn0 + np * 16) * stride + ks * 2 + laneOfs);
        ldm_x4(bl[np], bL + (wn0 + np * 16) * stride + ks * 2 + laneOfs);
    }
    #pragma unroll
    for (int mf = 0; mf < 2; mf++)
        #pragma unroll
        for (int np = 0; np < 2; np++) {
            mma_f16(c[mf][2 * np],     ah[mf], bh[np][0], bh[np][2]);
            mma_f16(c[mf][2 * np + 1], ah[mf], bh[np][1], bh[np][3]);
        }
    #pragma unroll
    for (int mf = 0; mf < 2; mf++)
        #pragma unroll
        for (int np = 0; np < 2; np++) {
            mma_f16(c[mf][2 * np],     ah[mf], bl[np][0], bl[np][2]);
            mma_f16(c[mf][2 * np + 1], ah[mf], bl[np][1], bl[np][3]);
        }
}

// ===========================================================================
// prep_w: W[K,N] fp32 -> Wt hi/lo [N,K] fp16.  grid (16, 32, 4), 256 thr
// ===========================================================================
__global__ void __launch_bounds__(256) prep_w_kernel(
    const float* __restrict__ W0, const float* __restrict__ W1,
    const float* __restrict__ W2, const float* __restrict__ W3)
{
    const float* Wz[4] = {W0, W1, W2, W3};
    const float* W = Wz[blockIdx.z];
    uint32_t* out_hi = (uint32_t*)g_wt_hi[blockIdx.z];
    uint32_t* out_lo = (uint32_t*)g_wt_lo[blockIdx.z];

    __shared__ float ts[64][33];
    const int k0 = blockIdx.x * 64, n0 = blockIdx.y * 32, tx = threadIdx.x;

    #pragma unroll
    for (int j = 0; j < 8; j++) {
        const int idx = tx + j * 256;
        const int k = idx >> 5, n = idx & 31;
        ts[k][n] = W[(size_t)(k0 + k) * Dd + n0 + n];
    }
    __syncthreads();

    #pragma unroll
    for (int j = 0; j < 4; j++) {
        const int idx = tx + j * 256;
        const int n = idx >> 5, kp = idx & 31;
        uint32_t h, l;
        splitp(ts[2 * kp][n], ts[2 * kp + 1][n], h, l);
        const size_t o = (size_t)(n0 + n) * (Dd / 2) + (k0 >> 1) + kp;
        out_hi[o] = h;
        out_lo[o] = l;
    }
}

// ===========================================================================
// prep_x: q,k,v fp32 -> fp16 hi plane only. grid (4096, 3), 256 thr
// ===========================================================================
__global__ void __launch_bounds__(256) prep_x_kernel(
    const float* __restrict__ q, const float* __restrict__ k, const float* __restrict__ v)
{
    const int z = blockIdx.y;
    const float* X = (z == 0) ? q : (z == 1) ? k : v;
    const int row = blockIdx.x, tx = threadIdx.x;
    float4 x = *(const float4*)&X[(size_t)row * Dd + tx * 4];
    uint2 hi;
    hi.x = pkh(x.x, x.y);
    hi.y = pkh(x.z, x.w);
    *(uint2*)((char*)g_x[z] + (size_t)row * 2048 + tx * 8) = hi;
}

__global__ void __launch_bounds__(256) zero_rs_kernel()
{
    const int i = (blockIdx.x * 256 + threadIdx.x) * 4;
    *(float4*)&g_rowsum[i] = make_float4(0.f, 0.f, 0.f, 0.f);
}

#define STRIDE 80
// stage: A hi 128x64B -> 10240 ; B hi 64x64B @10240 ; B lo @15360 ; stage 20480
#define G_STAGE 20480
#define G_BH 10240
#define G_BL 15360

// ===========================================================================
// qkv: Y = X@W + b. z==0 -> Q hi plane; z==1 -> K hi+lo; z==2 -> V^T hi+lo.
// CTA 128m x 64n, 256 thr, 2+ CTA/SM. grid (16 nt, 32 mt, 3). dyn smem 61440.
// ===========================================================================
__global__ void __launch_bounds__(256, 2) qkv_mma_kernel(
    const float* __restrict__ bq, const float* __restrict__ bk, const float* __restrict__ bv)
{
    extern __shared__ char sm[];
    const uint32_t sb = smem_u32(sm);

    const int z = blockIdx.z;
    const float* bias = (z == 0) ? bq : (z == 1) ? bk : bv;
    const char* XA = (const char*)g_x[z];
    const char* WtH = (const char*)g_wt_hi[z];
    const char* WtL = (const char*)g_wt_lo[z];

    const int tx = threadIdx.x, w = tx >> 5, lane = tx & 31;
    const int n0 = blockIdx.x * 64, m0 = blockIdx.y * 128;
    const int wm0 = (w & 3) * 32, wn0 = (w >> 2) * 32;
    const uint32_t laneOfs = (lane & 15) * STRIDE + (lane >> 4) * 16;

    const int arow = tx >> 1, acb = (tx & 1) * 32;     // A: 128 rows x 64B
    const int brow = tx >> 2, bcb = (tx & 3) * 16;     // B: 64 rows x 64B
    const size_t gar = (size_t)(m0 + arow) * 2048 + acb;
    const size_t gbr = (size_t)(n0 + brow) * 2048 + bcb;
    const uint32_t da = sb + arow * STRIDE + acb;
    const uint32_t db = sb + brow * STRIDE + bcb;

    float c[2][4][4] = {};

    #pragma unroll
    for (int p = 0; p < 2; p++) {
        const int k2 = p * 64;
        cpa16(da + p * G_STAGE,      XA + gar + k2);
        cpa16(da + p * G_STAGE + 16, XA + gar + k2 + 16);
        cpa16(db + p * G_STAGE + G_BH, WtH + gbr + k2);
        cpa16(db + p * G_STAGE + G_BL, WtL + gbr + k2);
        CPA_COMMIT();
    }

    for (int it = 0; it < 32; it++) {
        if (it == 31) { CPA_WAIT0(); } else { CPA_WAIT1(); }
        __syncthreads();
        if (it + 2 < 32) {
            const int st = (it + 2) % 3;
            const int k2 = (it + 2) * 64;
            cpa16(da + st * G_STAGE,      XA + gar + k2);
            cpa16(da + st * G_STAGE + 16, XA + gar + k2 + 16);
            cpa16(db + st * G_STAGE + G_BH, WtH + gbr + k2);
            cpa16(db + st * G_STAGE + G_BL, WtL + gbr + k2);
            CPA_COMMIT();
        }
        const uint32_t cur = sb + (it % 3) * G_STAGE;
        wtile2(c, cur, cur + G_BH, cur + G_BL, wm0, wn0, 0,  laneOfs, STRIDE);
        wtile2(c, cur, cur + G_BH, cur + G_BL, wm0, wn0, 16, laneOfs, STRIDE);
    }

    // epilogue: bias + store (layout depends on z)
    const int g = lane >> 2, t2 = (lane & 3) * 2;
    #pragma unroll
    for (int mf = 0; mf < 2; mf++)
        #pragma unroll
        for (int nf = 0; nf < 4; nf++) {
            const int n = n0 + wn0 + nf * 8 + t2;
            const int h = n >> 6, dc = n & (DK - 1);
            const float bf0 = bias[n], bf1 = bias[n + 1];
            #pragma unroll
            for (int rr = 0; rr < 2; rr++) {
                const int m = m0 + wm0 + mf * 16 + g + rr * 8;
                const int bb = m >> 11, s = m & (Ss - 1);
                float f0 = c[mf][nf][2 * rr] + bf0;
                float f1 = c[mf][nf][2 * rr + 1] + bf1;
                if (z == 0) {
                    const size_t eo = ((((size_t)(bb * Hh + h)) * Ss + s) * DK + dc) * 2;
                    *(uint32_t*)((char*)g_qh + eo) = pkh(f0, f1);
                } else if (z == 1) {
                    uint32_t hw, lw;
                    splitp(f0, f1, hw, lw);
                    const size_t eo = ((((size_t)(bb * Hh + h)) * Ss + s) * DK + dc) * 2;
                    *(uint32_t*)((char*)g_kh_hi + eo) = hw;
                    *(uint32_t*)((char*)g_kh_lo + eo) = lw;
                } else {
                    // V^T: vt[(bb*Hh+h)*DK + dc][s]  (fused transpose)
                    uint32_t hw, lw;
                    splitp(f0, f1, hw, lw);
                    const size_t r0 = (((size_t)(bb * Hh + h)) * DK + dc) * Ss + s;
                    ((unsigned short*)g_vt_hi)[r0]      = (unsigned short)(hw & 0xFFFF);
                    ((unsigned short*)g_vt_hi)[r0 + Ss] = (unsigned short)(hw >> 16);
                    ((unsigned short*)g_vt_lo)[r0]      = (unsigned short)(lw & 0xFFFF);
                    ((unsigned short*)g_vt_lo)[r0 + Ss] = (unsigned short)(lw >> 16);
                }
            }
        }
}

// ===========================================================================
// scores: e = exp(QK^T*0.125) -> fp16 hi plane + rowsums. CTA 128q x 64k.
// grid (32 kt, 16 qt, 32 bh), 256 thr, 2 CTA/SM. dyn smem 37376.
// QH 0 (18432) KH 18432 (9216) KL 27648 (9216) rowpart @36864
// ===========================================================================
#define SC_STRIDE 144
__global__ void __launch_bounds__(256, 2) scores_mma_kernel()
{
    extern __shared__ char sm[];
    const uint32_t sb = smem_u32(sm);
    float* rowpart = (float*)(sm + 36864);

    const int bh = blockIdx.z, tx = threadIdx.x, w = tx >> 5, lane = tx & 31;
    const int kb0 = blockIdx.x * 64, q0 = blockIdx.y * 128;
    const int wm0 = (w & 3) * 32, wn0 = (w >> 2) * 32;
    const uint32_t laneOfs = (lane & 15) * SC_STRIDE + (lane >> 4) * 16;

    const char* QA = (const char*)g_qh    + (size_t)bh * Ss * 128;
    const char* KH = (const char*)g_kh_hi + (size_t)bh * Ss * 128;
    const char* KL = (const char*)g_kh_lo + (size_t)bh * Ss * 128;

    if (tx < 128) rowpart[tx] = 0.f;

    #pragma unroll
    for (int j = 0; j < 4; j++) {           // Q hi: 128 rows x 128B
        const int idx = tx + j * 256;
        const int row = idx >> 3, cb = (idx & 7) * 16;
        cpa16(sb + row * SC_STRIDE + cb, QA + (size_t)(q0 + row) * 128 + cb);
    }
    #pragma unroll
    for (int j = 0; j < 2; j++) {           // K hi+lo: 64 rows x 128B each
        const int idx = tx + j * 256;
        const int row = idx >> 3, cb = (idx & 7) * 16;
        const uint32_t d = sb + 18432 + row * SC_STRIDE + cb;
        cpa16(d + 0,    KH + (size_t)(kb0 + row) * 128 + cb);
        cpa16(d + 9216, KL + (size_t)(kb0 + row) * 128 + cb);
    }
    CPA_COMMIT();
    CPA_WAIT0();
    __syncthreads();

    float c[2][4][4] = {};
    wtile2(c, sb, sb + 18432, sb + 27648, wm0, wn0, 0,  laneOfs, SC_STRIDE);
    wtile2(c, sb, sb + 18432, sb + 27648, wm0, wn0, 16, laneOfs, SC_STRIDE);
    wtile2(c, sb, sb + 18432, sb + 27648, wm0, wn0, 32, laneOfs, SC_STRIDE);
    wtile2(c, sb, sb + 18432, sb + 27648, wm0, wn0, 48, laneOfs, SC_STRIDE);

    const int g = lane >> 2, t2 = (lane & 3) * 2;
    char* SC = (char*)g_sc;
    float part[2][2] = {};
    #pragma unroll
    for (int mf = 0; mf < 2; mf++)
        #pragma unroll
        for (int nf = 0; nf < 4; nf++) {
            const int kc = kb0 + wn0 + nf * 8 + t2;
            #pragma unroll
            for (int rr = 0; rr < 2; rr++) {
                const int qr = q0 + wm0 + mf * 16 + g + rr * 8;
                float e0 = __expf(c[mf][nf][2 * rr] * 0.125f);
                float e1 = __expf(c[mf][nf][2 * rr + 1] * 0.125f);
                part[mf][rr] += e0 + e1;
                const size_t eo = (((size_t)bh * Ss + qr) * Ss + kc) * 2;
                *(uint32_t*)(SC + eo) = pkh(e0, e1);
            }
        }
    #pragma unroll
    for (int mf = 0; mf < 2; mf++)
        #pragma unroll
        for (int rr = 0; rr < 2; rr++) {
            float p = part[mf][rr];
            p += __shfl_xor_sync(~0u, p, 1);
            p += __shfl_xor_sync(~0u, p, 2);
            if ((lane & 3) == 0)
                atomicAdd(&rowpart[wm0 + mf * 16 + rr * 8 + g], p);
        }
    __syncthreads();
    if (tx < 128)
        atomicAdd(&g_rowsum[(size_t)bh * Ss + q0 + tx], rowpart[tx]);
}

// ===========================================================================
// ctx: C = (P@V)/s -> fp16 hi plane; also writes normalized attn fp32.
// CTA 128m x 64n, 256 thr, 2 CTA/SM. grid (16 mt, 32 bh). dyn smem 61952.
// stage = G_STAGE; inv_s @61440
// ===========================================================================
__global__ void __launch_bounds__(256, 2) ctx_mma_kernel(float* __restrict__ attn)
{
    extern __shared__ char sm[];
    const uint32_t sb = smem_u32(sm);
    float* inv_s = (float*)(sm + 61440);

    const int bh = blockIdx.y, tx = threadIdx.x, w = tx >> 5, lane = tx & 31;
    const int m0 = blockIdx.x * 128;
    const int wm0 = (w & 3) * 32, wn0 = (w >> 2) * 32;
    const uint32_t laneOfs = (lane & 15) * STRIDE + (lane >> 4) * 16;

    const char* SC  = (const char*)g_sc    + (size_t)bh * Ss * 4096;
    const char* VTH = (const char*)g_vt_hi + (size_t)bh * DK * 4096;
    const char* VTL = (const char*)g_vt_lo + (size_t)bh * DK * 4096;

    if (tx < 128) inv_s[tx] = 1.0f / g_rowsum[(size_t)bh * Ss + m0 + tx];

    const int arow = tx >> 1, acb = (tx & 1) * 32;
    const int brow = tx >> 2, bcb = (tx & 3) * 16;
    const size_t gar = (size_t)(m0 + arow) * 4096 + acb;
    const size_t gbr = (size_t)brow * 4096 + bcb;
    const uint32_t da = sb + arow * STRIDE + acb;
    const uint32_t db = sb + brow * STRIDE + bcb;

    float c[2][4][4] = {};

    #pragma unroll
    for (int p = 0; p < 2; p++) {
        const int k2 = p * 64;
        cpa16(da + p * G_STAGE,      SC + gar + k2);
        cpa16(da + p * G_STAGE + 16, SC + gar + k2 + 16);
        cpa16(db + p * G_STAGE + G_BH, VTH + gbr + k2);
        cpa16(db + p * G_STAGE + G_BL, VTL + gbr + k2);
        CPA_COMMIT();
    }

    for (int it = 0; it < 64; it++) {
        if (it == 63) { CPA_WAIT0(); } else { CPA_WAIT1(); }
        __syncthreads();
        if (it + 2 < 64) {
            const int st = (it + 2) % 3;
            const int k2 = (it + 2) * 64;
            cpa16(da + st * G_STAGE,      SC + gar + k2);
            cpa16(da + st * G_STAGE + 16, SC + gar + k2 + 16);
            cpa16(db + st * G_STAGE + G_BH, VTH + gbr + k2);
            cpa16(db + st * G_STAGE + G_BL, VTL + gbr + k2);
            CPA_COMMIT();
        }
        const int st = it % 3;
        const uint32_t cur = sb + st * G_STAGE;
        const int k0 = it * 32;

        // normalized attn fp32 write for this 128x32 block (from A hi smem, uint4)
        #pragma unroll
        for (int j = 0; j < 2; j++) {
            const int idx = tx + j * 256;
            const int row = idx >> 2, c8 = (idx & 3) * 8;
            uint4 hv = *(uint4*)(sm + st * G_STAGE + row * STRIDE + c8 * 2);
            const float is = inv_s[row];
            float2 p0 = uph(hv.x), p1 = uph(hv.y), p2 = uph(hv.z), p3 = uph(hv.w);
            float* dst = &attn[((size_t)bh * Ss + m0 + row) * Ss + k0 + c8];
            *(float4*)dst = make_float4(p0.x * is, p0.y * is, p1.x * is, p1.y * is);
            *(float4*)(dst + 4) = make_float4(p2.x * is, p2.y * is, p3.x * is, p3.y * is);
        }

        wtile2(c, cur, cur + G_BH, cur + G_BL, wm0, wn0, 0,  laneOfs, STRIDE);
        wtile2(c, cur, cur + G_BH, cur + G_BL, wm0, wn0, 16, laneOfs, STRIDE);
    }

    // epilogue: scale by inv_s, store ctx hi plane
    const int g = lane >> 2, t2 = (lane & 3) * 2;
    const int b = bh >> 4, h = bh & (Hh - 1);
    #pragma unroll
    for (int mf = 0; mf < 2; mf++)
        #pragma unroll
        for (int nf = 0; nf < 4; nf++) {
            const int dc = wn0 + nf * 8 + t2;
            #pragma unroll
            for (int rr = 0; rr < 2; rr++) {
                const int sl = wm0 + mf * 16 + g + rr * 8;
                const float is = inv_s[sl];
                float f0 = c[mf][nf][2 * rr] * is;
                float f1 = c[mf][nf][2 * rr + 1] * is;
                const size_t eo = (((size_t)(b * Ss + m0 + sl)) * Dd + h * DK + dc) * 2;
                *(uint32_t*)((char*)g_ctx + eo) = pkh(f0, f1);
            }
        }
}

// ===========================================================================
// out: out = ctx @ W_o + b_o fp32. CTA 128m x 64n, 256 thr, 2 CTA/SM.
// grid (16 nt, 32 mt). dyn smem 61440.
// ===========================================================================
__global__ void __launch_bounds__(256, 2) out_mma_kernel(
    const float* __restrict__ bias, float* __restrict__ out)
{
    extern __shared__ char sm[];
    const uint32_t sb = smem_u32(sm);

    const int tx = threadIdx.x, w = tx >> 5, lane = tx & 31;
    const int n0 = blockIdx.x * 64, m0 = blockIdx.y * 128;
    const int wm0 = (w & 3) * 32, wn0 = (w >> 2) * 32;
    const uint32_t laneOfs = (lane & 15) * STRIDE + (lane >> 4) * 16;

    const char* CA = (const char*)g_ctx;
    const char* WtH = (const char*)g_wt_hi[3];
    const char* WtL = (const char*)g_wt_lo[3];

    const int arow = tx >> 1, acb = (tx & 1) * 32;
    const int brow = tx >> 2, bcb = (tx & 3) * 16;
    const size_t gar = (size_t)(m0 + arow) * 2048 + acb;
    const size_t gbr = (size_t)(n0 + brow) * 2048 + bcb;
    const uint32_t da = sb + arow * STRIDE + acb;
    const uint32_t db = sb + brow * STRIDE + bcb;

    float c[2][4][4] = {};

    #pragma unroll
    for (int p = 0; p < 2; p++) {
        const int k2 = p * 64;
        cpa16(da + p * G_STAGE,      CA + gar + k2);
        cpa16(da + p * G_STAGE + 16, CA + gar + k2 + 16);
        cpa16(db + p * G_STAGE + G_BH, WtH + gbr + k2);
        cpa16(db + p * G_STAGE + G_BL, WtL + gbr + k2);
        CPA_COMMIT();
    }

    for (int it = 0; it < 32; it++) {
        if (it == 31) { CPA_WAIT0(); } else { CPA_WAIT1(); }
        __syncthreads();
        if (it + 2 < 32) {
            const int st = (it + 2) % 3;
            const int k2 = (it + 2) * 64;
            cpa16(da + st * G_STAGE,      CA + gar + k2);
            cpa16(da + st * G_STAGE + 16, CA + gar + k2 + 16);
            cpa16(db + st * G_STAGE + G_BH, WtH + gbr + k2);
            cpa16(db + st * G_STAGE + G_BL, WtL + gbr + k2);
            CPA_COMMIT();
        }
        const uint32_t cur = sb + (it % 3) * G_STAGE;
        wtile2(c, cur, cur + G_BH, cur + G_BL, wm0, wn0, 0,  laneOfs, STRIDE);
        wtile2(c, cur, cur + G_BH, cur + G_BL, wm0, wn0, 16, laneOfs, STRIDE);
    }

    const int g = lane >> 2, t2 = (lane & 3) * 2;
    #pragma unroll
    for (int mf = 0; mf < 2; mf++)
        #pragma unroll
        for (int nf = 0; nf < 4; nf++) {
            const int n = n0 + wn0 + nf * 8 + t2;
            const float bf0 = bias[n], bf1 = bias[n + 1];
            #pragma unroll
            for (int rr = 0; rr < 2; rr++) {
                const int m = m0 + wm0 + mf * 16 + g + rr * 8;
                float2 val = make_float2(c[mf][nf][2 * rr] + bf0,
                                         c[mf][nf][2 * rr + 1] + bf1);
                *(float2*)&out[(size_t)m * Dd + n] = val;
            }
        }
}

// ===========================================================================
extern "C" void kernel_launch(void* const* d_in, const int* in_sizes, int n_in,
                              void* d_out, int out_size)
{
    const float* q   = (const float*)d_in[0];
    const float* k   = (const float*)d_in[1];
    const float* v   = (const float*)d_in[2];
    const float* W_q = (const float*)d_in[3];
    const float* b_q = (const float*)d_in[4];
    const float* W_k = (const float*)d_in[5];
    const float* b_k = (const float*)d_in[6];
    const float* W_v = (const float*)d_in[7];
    const float* b_v = (const float*)d_in[8];
    const float* W_o = (const float*)d_in[9];
    const float* b_o = (const float*)d_in[10];

    float* out  = (float*)d_out;
    float* attn = out + (size_t)Bb * Ss * Dd;

    static int smem_set = 0;
    if (!smem_set) {
        cudaFuncSetAttribute(qkv_mma_kernel,    cudaFuncAttributeMaxDynamicSharedMemorySize, 61440);
        cudaFuncSetAttribute(scores_mma_kernel, cudaFuncAttributeMaxDynamicSharedMemorySize, 37376);
        cudaFuncSetAttribute(ctx_mma_kernel,    cudaFuncAttributeMaxDynamicSharedMemorySize, 61952);
        cudaFuncSetAttribute(out_mma_kernel,    cudaFuncAttributeMaxDynamicSharedMemorySize, 61440);
        smem_set = 1;
    }

    prep_w_kernel<<<dim3(16, 32, 4), 256>>>(W_q, W_k, W_v, W_o);
    prep_x_kernel<<<dim3(4096, 3), 256>>>(q, k, v);
    zero_rs_kernel<<<64, 256>>>();
    qkv_mma_kernel<<<dim3(16, 32, 3), 256, 61440>>>(b_q, b_k, b_v);
    scores_mma_kernel<<<dim3(32, 16, 32), 256, 37376>>>();
    ctx_mma_kernel<<<dim3(16, 32), 256, 61952>>>(attn);
    out_mma_kernel<<<dim3(16, 32), 256, 61440>>>(b_o, out);
}